// round 9
// baseline (speedup 1.0000x reference)
#include <cuda_runtime.h>
#include <cstdint>

// out[b] = -(inp[b,:] . quad)^2 + inp[b,:] . linw + bias
// B = 16384, D = 4096, fp32. 256 MiB streaming read — HBM-bound.
//
// R9 (= R8 retry; container-level failure, theory untested): bulk-DMA
// pipeline. R1..R7 (LDG / ping-pong regs / cp.async) ALL pin at 73-77% DRAM:
// per-thread load issue couples to warp scheduling regardless of flavor.
// Thread 0 issues ONE cp.async.bulk (TMA/UBLKCP) per 16KB row with mbarrier
// complete_tx; warps never issue global loads. DEPTH=2 full/empty ring;
// consumers snapshot their float4s to regs, arrive-empty immediately, and
// run FMAs + reduction off the pipeline critical path.
// Hardening vs R8: canonical shared::cluster bulk spelling + proxy fence
// after mbarrier init.

#ifndef D_DIM
#define D_DIM 4096
#endif

constexpr int THREADS     = 256;           // 8 warps
constexpr int WARPS       = THREADS / 32;
constexpr int F4_PER_LANE = (D_DIM / WARPS) / 4 / 32;  // 4
constexpr int TILE_ROWS   = 16;
constexpr int DEPTH       = 2;
constexpr int ROW_BYTES   = D_DIM * 4;     // 16 KB

__device__ __forceinline__ uint32_t smem_u32(const void* p) {
    uint32_t a;
    asm("{ .reg .u64 t; cvta.to.shared.u64 t, %1; cvt.u32.u64 %0, t; }"
        : "=r"(a) : "l"(p));
    return a;
}

__device__ __forceinline__ void mbar_init(uint32_t mbar, uint32_t cnt) {
    asm volatile("mbarrier.init.shared.b64 [%0], %1;" :: "r"(mbar), "r"(cnt) : "memory");
}
__device__ __forceinline__ void mbar_expect_tx(uint32_t mbar, uint32_t bytes) {
    asm volatile("mbarrier.arrive.expect_tx.shared.b64 _, [%0], %1;"
                 :: "r"(mbar), "r"(bytes) : "memory");
}
__device__ __forceinline__ void mbar_arrive(uint32_t mbar) {
    asm volatile("mbarrier.arrive.shared.b64 _, [%0];" :: "r"(mbar) : "memory");
}
__device__ __forceinline__ void mbar_wait(uint32_t mbar, uint32_t parity) {
    uint32_t done;
    asm volatile(
        "{\n\t.reg .pred p;\n\t"
        "mbarrier.try_wait.parity.acquire.cta.shared::cta.b64 p, [%1], %2;\n\t"
        "selp.b32 %0, 1, 0, p;\n\t}"
        : "=r"(done) : "r"(mbar), "r"(parity) : "memory");
    if (!done) {
        asm volatile(
            "{\n\t.reg .pred P1;\n\t"
            "W_%=:\n\t"
            "mbarrier.try_wait.parity.acquire.cta.shared::cta.b64 P1, [%0], %1, 0x989680;\n\t"
            "@P1 bra.uni D_%=;\n\t"
            "bra.uni W_%=;\n\t"
            "D_%=:\n\t}"
            :: "r"(mbar), "r"(parity) : "memory");
    }
}
__device__ __forceinline__ void bulk_ld(uint32_t dst_smem, const void* src, uint32_t bytes,
                                        uint32_t mbar) {
    asm volatile(
        "cp.async.bulk.shared::cluster.global.mbarrier::complete_tx::bytes "
        "[%0], [%1], %2, [%3];"
        :: "r"(dst_smem), "l"(src), "r"(bytes), "r"(mbar) : "memory");
}

__global__ __launch_bounds__(THREADS)
void skinny_quad_kernel(const float* __restrict__ inp,
                        const float* __restrict__ quad,
                        const float* __restrict__ linw,
                        const float* __restrict__ linb,
                        float* __restrict__ out,
                        int B)
{
    __shared__ __align__(128) float4 s_x[DEPTH][D_DIM / 4];   // 32 KB ring
    __shared__ __align__(8) uint64_t s_full[DEPTH];
    __shared__ __align__(8) uint64_t s_empty[DEPTH];
    __shared__ float2 s_part[TILE_ROWS][WARPS];               // 1 KB

    const int tid  = threadIdx.x;
    const int lane = tid & 31;
    const int warp = tid >> 5;
    const int cbase = warp * (D_DIM / WARPS / 4);   // warp's 128-float4 chunk

    const uint32_t full0  = smem_u32(&s_full[0]);
    const uint32_t empty0 = smem_u32(&s_empty[0]);

    if (tid == 0) {
        #pragma unroll
        for (int s = 0; s < DEPTH; ++s) {
            mbar_init(full0  + 8u * s, 1);        // completes via expect_tx
            mbar_init(empty0 + 8u * s, THREADS);  // all threads arrive
        }
        asm volatile("fence.proxy.async.shared::cta;" ::: "memory");
    }

    // Weights into registers while barriers settle
    const float4* __restrict__ gq = reinterpret_cast<const float4*>(quad) + cbase;
    const float4* __restrict__ gl = reinterpret_cast<const float4*>(linw) + cbase;
    float4 q[F4_PER_LANE], l[F4_PER_LANE];
    #pragma unroll
    for (int i = 0; i < F4_PER_LANE; ++i) {
        q[i] = gq[i * 32 + lane];
        l[i] = gl[i * 32 + lane];
    }

    __syncthreads();   // barriers initialized before any use

    const int row0 = blockIdx.x * TILE_ROWS;
    const char* __restrict__ gbase =
        reinterpret_cast<const char*>(inp) + (size_t)row0 * ROW_BYTES;

    // Prologue: thread 0 issues rows 0..DEPTH-1 (stages fresh, no wait)
    if (tid == 0) {
        #pragma unroll
        for (int j = 0; j < DEPTH; ++j) {
            mbar_expect_tx(full0 + 8u * j, ROW_BYTES);
            bulk_ld(smem_u32(&s_x[j][0]), gbase + (size_t)j * ROW_BYTES,
                    ROW_BYTES, full0 + 8u * j);
        }
    }

    for (int r = 0; r < TILE_ROWS; ++r) {
        const int      st       = r & (DEPTH - 1);
        const uint32_t full_par = (r >> 1) & 1;   // k-th reuse completes parity k&1

        mbar_wait(full0 + 8u * st, full_par);

        // Snapshot this thread's 4 float4 into registers
        float4 x[F4_PER_LANE];
        #pragma unroll
        for (int i = 0; i < F4_PER_LANE; ++i)
            x[i] = s_x[st][cbase + i * 32 + lane];

        // Stage free as soon as values are in regs
        mbar_arrive(empty0 + 8u * st);

        // Producer: refill this stage once it drains
        if (tid == 0 && r + DEPTH < TILE_ROWS) {
            const int j = r + DEPTH;
            const uint32_t empty_par = ((j >> 1) - 1) & 1;
            mbar_wait(empty0 + 8u * st, empty_par);
            mbar_expect_tx(full0 + 8u * st, ROW_BYTES);
            bulk_ld(smem_u32(&s_x[st][0]), gbase + (size_t)j * ROW_BYTES,
                    ROW_BYTES, full0 + 8u * st);
        }

        // Compute off the pipeline critical path
        float sq = 0.f, sl = 0.f;
        #pragma unroll
        for (int i = 0; i < F4_PER_LANE; ++i) {
            sq = fmaf(x[i].x, q[i].x, sq);
            sq = fmaf(x[i].y, q[i].y, sq);
            sq = fmaf(x[i].z, q[i].z, sq);
            sq = fmaf(x[i].w, q[i].w, sq);
            sl = fmaf(x[i].x, l[i].x, sl);
            sl = fmaf(x[i].y, l[i].y, sl);
            sl = fmaf(x[i].z, l[i].z, sl);
            sl = fmaf(x[i].w, l[i].w, sl);
        }
        #pragma unroll
        for (int off = 16; off > 0; off >>= 1) {
            sq += __shfl_down_sync(0xFFFFFFFFu, sq, off);
            sl += __shfl_down_sync(0xFFFFFFFFu, sl, off);
        }
        if (lane == 0)
            s_part[r][warp] = make_float2(sq, sl);
    }

    __syncthreads();

    // Final cross-warp reduction: 8 threads per row
    if (tid < TILE_ROWS * WARPS) {
        const int row = tid >> 3;
        const int w   = tid & 7;
        const float2 p = s_part[row][w];
        float sq = p.x, sl = p.y;
        #pragma unroll
        for (int off = 4; off > 0; off >>= 1) {
            sq += __shfl_down_sync(0xFFFFFFFFu, sq, off, 8);
            sl += __shfl_down_sync(0xFFFFFFFFu, sl, off, 8);
        }
        if (w == 0) {
            const int orow = row0 + row;
            if (orow < B) {
                const float bias = *linb;
                out[orow] = fmaf(-sq, sq, sl + bias);
            }
        }
    }
}

extern "C" void kernel_launch(void* const* d_in, const int* in_sizes, int n_in,
                              void* d_out, int out_size)
{
    const float* inp  = (const float*)d_in[0];   // (B, D)
    const float* quad = (const float*)d_in[1];   // (D, 1)
    const float* linw = (const float*)d_in[2];   // (1, D)
    const float* linb = (const float*)d_in[3];   // (1,)
    float* out = (float*)d_out;

    const int B = in_sizes[0] / D_DIM;
    const int grid = (B + TILE_ROWS - 1) / TILE_ROWS;

    skinny_quad_kernel<<<grid, THREADS>>>(inp, quad, linw, linb, out, B);
}

// round 10
// speedup vs baseline: 1.1167x; 1.1167x over previous
#include <cuda_runtime.h>

// out[b] = -(inp[b,:] . quad)^2 + inp[b,:] . linw + bias
// B = 16384, D = 4096, fp32. 256 MiB streaming read — HBM/LTS-bound.
//
// R10: one-wave persistent partition. R1..R9 established that LDG, cp.async
// and TMA all pin at ~6.1-6.3 TB/s (the path-independent LTS cap), so the
// load path is done. What R4/R5 still paid was wave quantization: grid=1024
// over ~592 resident blocks = 1.73 waves -> makespan 2 -> ~13% idle tail.
// Now grid = 592 (4 blocks/SM x 148 SMs, pinned by __launch_bounds__(256,4)),
// each block owns a contiguous 27-28 row range: ONE fully-resident wave,
// max warps in flight for the whole kernel. Body is the proven R4 loop:
// warp-per-column-chunk, weights in 32 registers, 4 independent LDG.128 per
// row, per-row shuffle reduce (measured free vs deferred reduction).

#ifndef D_DIM
#define D_DIM 4096
#endif

constexpr int THREADS      = 256;            // 8 warps
constexpr int WARPS        = THREADS / 32;   // 8
constexpr int F4_PER_LANE  = (D_DIM / WARPS) / 4 / 32;  // 4
constexpr int NUM_SMS      = 148;
constexpr int BLOCKS_PER_SM = 4;
constexpr int GRID         = NUM_SMS * BLOCKS_PER_SM;   // 592
constexpr int MAX_ROWS     = 32;             // >= ceil(16384/592) = 28

__global__ __launch_bounds__(THREADS, BLOCKS_PER_SM)
void skinny_quad_kernel(const float* __restrict__ inp,
                        const float* __restrict__ quad,
                        const float* __restrict__ linw,
                        const float* __restrict__ linb,
                        float* __restrict__ out,
                        int B)
{
    __shared__ float2 s_part[MAX_ROWS][WARPS];   // 2 KB

    const int tid  = threadIdx.x;
    const int lane = tid & 31;
    const int warp = tid >> 5;
    const int cbase = warp * (D_DIM / WARPS / 4);   // warp's 128-float4 chunk

    // Weights in registers, loaded once per (persistent) block
    const float4* __restrict__ gq = reinterpret_cast<const float4*>(quad) + cbase;
    const float4* __restrict__ gl = reinterpret_cast<const float4*>(linw) + cbase;
    float4 q[F4_PER_LANE], l[F4_PER_LANE];
    #pragma unroll
    for (int i = 0; i < F4_PER_LANE; ++i) {
        q[i] = gq[i * 32 + lane];
        l[i] = gl[i * 32 + lane];
    }

    // Balanced contiguous row range for this block: 27 or 28 rows
    const int bid  = blockIdx.x;
    const int rbeg = (int)(((long long)bid * B) / GRID);
    const int rend = (int)(((long long)(bid + 1) * B) / GRID);
    const int nrows = rend - rbeg;

    const float4* __restrict__ xbase =
        reinterpret_cast<const float4*>(inp) + (size_t)rbeg * (D_DIM / 4) + cbase;

    #pragma unroll 2
    for (int r = 0; r < nrows; ++r) {
        const float4* __restrict__ xr = xbase + (size_t)r * (D_DIM / 4);

        // 4 independent 128-bit loads (2KB contiguous per warp-row)
        float4 x[F4_PER_LANE];
        #pragma unroll
        for (int i = 0; i < F4_PER_LANE; ++i)
            x[i] = xr[i * 32 + lane];

        float sq = 0.f, sl = 0.f;
        #pragma unroll
        for (int i = 0; i < F4_PER_LANE; ++i) {
            sq = fmaf(x[i].x, q[i].x, sq);
            sq = fmaf(x[i].y, q[i].y, sq);
            sq = fmaf(x[i].z, q[i].z, sq);
            sq = fmaf(x[i].w, q[i].w, sq);
            sl = fmaf(x[i].x, l[i].x, sl);
            sl = fmaf(x[i].y, l[i].y, sl);
            sl = fmaf(x[i].z, l[i].z, sl);
            sl = fmaf(x[i].w, l[i].w, sl);
        }

        // per-row warp reduction (measured ~free vs deferred reduction)
        #pragma unroll
        for (int off = 16; off > 0; off >>= 1) {
            sq += __shfl_down_sync(0xFFFFFFFFu, sq, off);
            sl += __shfl_down_sync(0xFFFFFFFFu, sl, off);
        }
        if (lane == 0)
            s_part[r][warp] = make_float2(sq, sl);
    }

    __syncthreads();

    // Final cross-warp reduction: 8 threads per row (subgroups of 8 stay
    // inside a warp since 8 | 32)
    if (tid < nrows * WARPS) {
        const int row = tid >> 3;        // 0..nrows-1
        const int w   = tid & 7;         // 0..7
        const float2 p = s_part[row][w];
        float sq = p.x, sl = p.y;

        #pragma unroll
        for (int off = 4; off > 0; off >>= 1) {
            sq += __shfl_down_sync(0xFFFFFFFFu, sq, off, 8);
            sl += __shfl_down_sync(0xFFFFFFFFu, sl, off, 8);
        }

        if (w == 0) {
            const float bias = *linb;
            out[rbeg + row] = fmaf(-sq, sq, sl + bias);
        }
    }
}

extern "C" void kernel_launch(void* const* d_in, const int* in_sizes, int n_in,
                              void* d_out, int out_size)
{
    const float* inp  = (const float*)d_in[0];   // (B, D)
    const float* quad = (const float*)d_in[1];   // (D, 1)
    const float* linw = (const float*)d_in[2];   // (1, D)
    const float* linb = (const float*)d_in[3];   // (1,)
    float* out = (float*)d_out;

    const int B = in_sizes[0] / D_DIM;

    skinny_quad_kernel<<<GRID, THREADS>>>(inp, quad, linw, linb, out, B);
}

// round 11
// speedup vs baseline: 1.1344x; 1.0159x over previous
#include <cuda_runtime.h>

// out[b] = -(inp[b,:] . quad)^2 + inp[b,:] . linw + bias
// B = 16384, D = 4096, fp32. 256 MiB streaming read — bound by the
// path-independent LTS/HBM cap (~6.3 TB/s measured across LDG/cp.async/TMA).
//
// R11: finer scheduling quantum. R10 proved a static one-wave partition is
// WORSE (spread-induced idle can't be backfilled); R4/R5's multi-wave
// schedule self-balances. So: identical R4 body (reg-resident weights,
// 4 independent LDG.128 per warp-row, per-row shuffle reduce), but
// ROWS_PER_BLOCK 16 -> 8, grid 1024 -> 2048 (~3.5 waves over ~592 resident
// blocks). Smaller quantum -> work stealing packs the per-CTA completion
// spread much tighter -> tail loss ~6% -> ~2%.

#ifndef D_DIM
#define D_DIM 4096
#endif

constexpr int THREADS        = 256;            // 8 warps
constexpr int WARPS          = THREADS / 32;   // 8
constexpr int F4_PER_LANE    = (D_DIM / WARPS) / 4 / 32;  // 4
constexpr int ROWS_PER_BLOCK = 8;

__global__ __launch_bounds__(THREADS)
void skinny_quad_kernel(const float* __restrict__ inp,
                        const float* __restrict__ quad,
                        const float* __restrict__ linw,
                        const float* __restrict__ linb,
                        float* __restrict__ out,
                        int B)
{
    __shared__ float2 s_part[ROWS_PER_BLOCK][WARPS];   // 512 B

    const int tid  = threadIdx.x;
    const int lane = tid & 31;
    const int warp = tid >> 5;
    const int cbase = warp * (D_DIM / WARPS / 4);   // warp's 128-float4 chunk

    // Weights in registers, loaded once per block (L2-hot after first wave)
    const float4* __restrict__ gq = reinterpret_cast<const float4*>(quad) + cbase;
    const float4* __restrict__ gl = reinterpret_cast<const float4*>(linw) + cbase;
    float4 q[F4_PER_LANE], l[F4_PER_LANE];
    #pragma unroll
    for (int i = 0; i < F4_PER_LANE; ++i) {
        q[i] = gq[i * 32 + lane];
        l[i] = gl[i * 32 + lane];
    }

    const int row0 = blockIdx.x * ROWS_PER_BLOCK;

    #pragma unroll 2
    for (int r = 0; r < ROWS_PER_BLOCK; ++r) {
        const float4* __restrict__ xr =
            reinterpret_cast<const float4*>(inp + (size_t)(row0 + r) * D_DIM) + cbase;

        // 4 independent 128-bit loads (2KB contiguous per warp-row)
        float4 x[F4_PER_LANE];
        #pragma unroll
        for (int i = 0; i < F4_PER_LANE; ++i)
            x[i] = xr[i * 32 + lane];

        float sq = 0.f, sl = 0.f;
        #pragma unroll
        for (int i = 0; i < F4_PER_LANE; ++i) {
            sq = fmaf(x[i].x, q[i].x, sq);
            sq = fmaf(x[i].y, q[i].y, sq);
            sq = fmaf(x[i].z, q[i].z, sq);
            sq = fmaf(x[i].w, q[i].w, sq);
            sl = fmaf(x[i].x, l[i].x, sl);
            sl = fmaf(x[i].y, l[i].y, sl);
            sl = fmaf(x[i].z, l[i].z, sl);
            sl = fmaf(x[i].w, l[i].w, sl);
        }

        // per-row warp reduction (measured ~free)
        #pragma unroll
        for (int off = 16; off > 0; off >>= 1) {
            sq += __shfl_down_sync(0xFFFFFFFFu, sq, off);
            sl += __shfl_down_sync(0xFFFFFFFFu, sl, off);
        }
        if (lane == 0)
            s_part[r][warp] = make_float2(sq, sl);
    }

    __syncthreads();

    // Final cross-warp reduction: 8 threads per row (64 threads active;
    // 8-thread subgroups stay inside one warp)
    if (tid < ROWS_PER_BLOCK * WARPS) {
        const int row = tid >> 3;        // 0..7
        const int w   = tid & 7;         // 0..7
        const float2 p = s_part[row][w];
        float sq = p.x, sl = p.y;

        #pragma unroll
        for (int off = 4; off > 0; off >>= 1) {
            sq += __shfl_down_sync(0xFFFFFFFFu, sq, off, 8);
            sl += __shfl_down_sync(0xFFFFFFFFu, sl, off, 8);
        }

        if (w == 0) {
            const int orow = row0 + row;
            if (orow < B) {
                const float bias = *linb;
                out[orow] = fmaf(-sq, sq, sl + bias);
            }
        }
    }
}

extern "C" void kernel_launch(void* const* d_in, const int* in_sizes, int n_in,
                              void* d_out, int out_size)
{
    const float* inp  = (const float*)d_in[0];   // (B, D)
    const float* quad = (const float*)d_in[1];   // (D, 1)
    const float* linw = (const float*)d_in[2];   // (1, D)
    const float* linb = (const float*)d_in[3];   // (1,)
    float* out = (float*)d_out;

    const int B = in_sizes[0] / D_DIM;
    const int grid = (B + ROWS_PER_BLOCK - 1) / ROWS_PER_BLOCK;

    skinny_quad_kernel<<<grid, THREADS>>>(inp, quad, linw, linb, out, B);
}